// round 1
// baseline (speedup 1.0000x reference)
#include <cuda_runtime.h>

#define N_NODES 500000
#define N_EDGES 1250000
#define N_SUB   50000
#define N_GRAPH 64

typedef unsigned long long u64;

// ---------------- scratch (device globals; no allocation allowed) -----------
__device__ float g_x[N_NODES * 64];    // node features (128 MB)
__device__ float g_m[N_NODES * 64];    // messages      (128 MB)
__device__ float g_agg[N_NODES * 64];  // aggregated    (128 MB)
__device__ float g_u[4 * 100 * 64];    // fused table: ze@Wright^T + b   (layers 1..4)
__device__ float g_Bm[4 * 64 * 64];    // fused weight: Wleft^T @ G      (layers 1..4)
__device__ float g_v[4 * 100 * 64];    // fused table: u @ G             (layers 1..4)
__device__ float g_t0m[100 * 64];      // fused table: ztab0 @ G0        (layer 0)
__device__ float g_gsum[64 * 64];      // graph pooled sums

// ---------------- helpers ---------------------------------------------------
__device__ __forceinline__ u64 fma2(u64 a, u64 b, u64 c) {
    u64 d;
    asm("fma.rn.f32x2 %0, %1, %2, %3;" : "=l"(d) : "l"(a), "l"(b), "l"(c));
    return d;
}
__device__ __forceinline__ u64 pk(float a, float b) {
    u64 r;
    asm("mov.b64 %0, {%1, %2};" : "=l"(r) : "f"(a), "f"(b));
    return r;
}
__device__ __forceinline__ float red2(u64 v) {
    float a, b;
    asm("mov.b64 {%0, %1}, %2;" : "=f"(a), "=f"(b) : "l"(v));
    return a + b;
}
__device__ __forceinline__ float sigm(float x)  { return __fdividef(1.0f, 1.0f + __expf(-x)); }
__device__ __forceinline__ float tanh_(float x) { return __fdividef(2.0f, 1.0f + __expf(-2.0f * x)) - 1.0f; }
__device__ __forceinline__ float elu_(float x)  { return x > 0.0f ? x : (__expf(x) - 1.0f); }

// ---------------- init / precompute ------------------------------------------
__global__ void k_zero_agg() {
    int idx = blockIdx.x * 256 + threadIdx.x;  // exactly N_NODES*16 threads
    ((float4*)g_agg)[idx] = make_float4(0.f, 0.f, 0.f, 0.f);
}

__global__ void k_zero_gsum() {
    int i = blockIdx.x * 256 + threadIdx.x;
    if (i < 4096) g_gsum[i] = 0.f;
}

// u_l[r][o] = tf_b[l][o] + sum_k ztab[l+1][r][k] * tfW[l][o][64+k]
// B_l[o][k] = sum_t tfW[l][t][k] * G[l+1][t][o]
// t0m[r][o] = sum_k ztab[0][r][k] * G[0][k][o]
__global__ void k_pre1(const float* __restrict__ ztab, const float* __restrict__ tfW,
                       const float* __restrict__ tfb, const float* __restrict__ ggcW) {
    int i = blockIdx.x * blockDim.x + threadIdx.x;
    if (i < 25600) {
        int j = i / 6400, r = (i % 6400) / 64, o = i % 64;
        const float* zt = ztab + (j + 1) * 6400 + r * 64;
        const float* w  = tfW + j * 8192 + o * 128 + 64;
        float acc = tfb[j * 64 + o];
        #pragma unroll
        for (int k = 0; k < 64; k++) acc += zt[k] * w[k];
        g_u[i] = acc;
    } else if (i < 41984) {
        int ii = i - 25600;
        int j = ii / 4096, o = (ii % 4096) / 64, k = ii % 64;
        const float* g = ggcW + (j + 1) * 4096 + o;
        const float* w = tfW + j * 8192 + k;
        float acc = 0.f;
        #pragma unroll
        for (int t = 0; t < 64; t++) acc += w[t * 128] * g[t * 64];
        g_Bm[ii] = acc;
    } else if (i < 48384) {
        int ii = i - 41984;
        int r = ii / 64, o = ii % 64;
        float acc = 0.f;
        #pragma unroll
        for (int k = 0; k < 64; k++) acc += ztab[r * 64 + k] * ggcW[k * 64 + o];
        g_t0m[ii] = acc;
    }
}

// v_l[r][o] = sum_t u_l[r][t] * G[l+1][t][o]
__global__ void k_pre2(const float* __restrict__ ggcW) {
    int i = blockIdx.x * blockDim.x + threadIdx.x;
    if (i >= 25600) return;
    int j = i / 6400, r = (i % 6400) / 64, o = i % 64;
    const float* urow = g_u + j * 6400 + r * 64;
    const float* g = ggcW + (j + 1) * 4096 + o;
    float acc = 0.f;
    #pragma unroll
    for (int t = 0; t < 64; t++) acc += urow[t] * g[t * 64];
    g_v[i] = acc;
}

// ---------------- layer 0: pure lookups --------------------------------------
__global__ void k_layer0(const int* __restrict__ z, const float* __restrict__ ztab) {
    int idx = blockIdx.x * 256 + threadIdx.x;  // exactly N_NODES*16
    int n = idx >> 4, c = idx & 15;
    int r = __ldg(z + n);
    float4 a = ((const float4*)(ztab + r * 64))[c];
    ((float4*)(g_x + (size_t)n * 64))[c] = a;
    float4 b = ((const float4*)(g_t0m + r * 64))[c];
    ((float4*)(g_m + (size_t)n * 64))[c] = b;
}

// ---------------- layers 1..4 pre: xnew = x@Wl^T + u[z];  m = x@B^T + v[z] ----
__global__ void __launch_bounds__(256) k_pre(const int* __restrict__ z,
                                             const float* __restrict__ tfW, int j) {
    __shared__ float sW[4096];  // tfW[j][o][0:64], row o contiguous
    __shared__ float sB[4096];  // B[j][o][k], row o contiguous
    int tid = threadIdx.x;
    for (int i = tid; i < 4096; i += 256) {
        int o = i >> 6, k = i & 63;
        sW[i] = tfW[j * 8192 + o * 128 + k];
        sB[i] = g_Bm[j * 4096 + i];
    }
    __syncthreads();
    int n = blockIdx.x * 256 + tid;
    if (n >= N_NODES) return;

    u64 X[32];
    {
        const float4* xr = (const float4*)(g_x + (size_t)n * 64);
        #pragma unroll
        for (int i = 0; i < 16; i++) {
            float4 t = xr[i];
            X[2 * i] = pk(t.x, t.y);
            X[2 * i + 1] = pk(t.z, t.w);
        }
    }
    int zr = __ldg(z + n);
    const float* urow = g_u + j * 6400 + zr * 64;
    const float* vrow = g_v + j * 6400 + zr * 64;
    float4* xout = (float4*)(g_x + (size_t)n * 64);
    float4* mout = (float4*)(g_m + (size_t)n * 64);

    #pragma unroll 1
    for (int o4 = 0; o4 < 16; o4++) {
        float rx[4], rm[4];
        #pragma unroll
        for (int q = 0; q < 4; q++) {
            int o = o4 * 4 + q;
            const u64* w = (const u64*)(sW + o * 64);
            const u64* b = (const u64*)(sB + o * 64);
            u64 ax = 0ull, am = 0ull;
            #pragma unroll
            for (int k = 0; k < 32; k++) {
                ax = fma2(X[k], w[k], ax);
                am = fma2(X[k], b[k], am);
            }
            rx[q] = red2(ax) + __ldg(urow + o);
            rm[q] = red2(am) + __ldg(vrow + o);
        }
        xout[o4] = make_float4(rx[0], rx[1], rx[2], rx[3]);
        mout[o4] = make_float4(rm[0], rm[1], rm[2], rm[3]);
    }
}

// ---------------- edge scatter: agg[dst] += m[src] ----------------------------
__global__ void k_scatter(const int* __restrict__ src, const int* __restrict__ dst) {
    int idx = blockIdx.x * 256 + threadIdx.x;  // exactly N_EDGES*16
    int e = idx >> 4, c = idx & 15;
    int s = __ldg(src + e), t = __ldg(dst + e);
    float4 v = ((const float4*)(g_m + (size_t)s * 64))[c];
    float* o = g_agg + (size_t)t * 64 + c * 4;
    atomicAdd(o + 0, v.x);
    atomicAdd(o + 1, v.y);
    atomicAdd(o + 2, v.z);
    atomicAdd(o + 3, v.w);
}

// ---------------- GRU cell update (also re-zeroes agg for next layer) ---------
__global__ void __launch_bounds__(256) k_gru(const float* __restrict__ wih,
                                             const float* __restrict__ whh,
                                             const float* __restrict__ bih,
                                             const float* __restrict__ bhh) {
    extern __shared__ float sm[];
    float* sWih = sm;            // 192*64
    float* sWhh = sm + 12288;    // 192*64
    float* sb   = sm + 24576;    // 192 bih | 192 bhh
    int tid = threadIdx.x;
    for (int i = tid; i < 12288; i += 256) {
        sWih[i] = wih[i];
        sWhh[i] = whh[i];
    }
    if (tid < 192) {
        sb[tid] = bih[tid];
        sb[192 + tid] = bhh[tid];
    }
    __syncthreads();
    int n = blockIdx.x * 256 + tid;
    if (n >= N_NODES) return;

    u64 A[32], H[32];
    float4* ar = (float4*)(g_agg + (size_t)n * 64);
    const float4* hr = (const float4*)(g_x + (size_t)n * 64);
    #pragma unroll
    for (int i = 0; i < 16; i++) {
        float4 t = ar[i];
        A[2 * i] = pk(t.x, t.y);
        A[2 * i + 1] = pk(t.z, t.w);
    }
    float4 z4 = make_float4(0.f, 0.f, 0.f, 0.f);
    #pragma unroll
    for (int i = 0; i < 16; i++) ar[i] = z4;  // zero agg for next layer's scatter
    #pragma unroll
    for (int i = 0; i < 16; i++) {
        float4 t = hr[i];
        H[2 * i] = pk(t.x, t.y);
        H[2 * i + 1] = pk(t.z, t.w);
    }
    float* xrow = g_x + (size_t)n * 64;

    #pragma unroll 1
    for (int d = 0; d < 64; d++) {
        const u64* wr = (const u64*)(sWih + d * 64);
        const u64* wz = (const u64*)(sWih + 4096 + d * 64);
        const u64* wn = (const u64*)(sWih + 8192 + d * 64);
        const u64* vr = (const u64*)(sWhh + d * 64);
        const u64* vz = (const u64*)(sWhh + 4096 + d * 64);
        const u64* vn = (const u64*)(sWhh + 8192 + d * 64);
        u64 air = 0, aiz = 0, ain = 0, ahr = 0, ahz = 0, ahn = 0;
        #pragma unroll
        for (int k = 0; k < 32; k++) {
            u64 a = A[k], h = H[k];
            air = fma2(a, wr[k], air);
            aiz = fma2(a, wz[k], aiz);
            ain = fma2(a, wn[k], ain);
            ahr = fma2(h, vr[k], ahr);
            ahz = fma2(h, vz[k], ahz);
            ahn = fma2(h, vn[k], ahn);
        }
        float r  = sigm(red2(air) + sb[d]       + red2(ahr) + sb[192 + d]);
        float u  = sigm(red2(aiz) + sb[64 + d]  + red2(ahz) + sb[256 + d]);
        float nn = tanh_(red2(ain) + sb[128 + d] + r * (red2(ahn) + sb[320 + d]));
        float hd = xrow[d];  // old value (not yet overwritten at this d)
        xrow[d] = (1.0f - u) * nn + u * hd;
    }
}

// ---------------- pooling (node -> graph, sums compose) -----------------------
__global__ void k_pool(const int* __restrict__ n2s, const int* __restrict__ s2g) {
    int idx = blockIdx.x * 256 + threadIdx.x;  // exactly N_NODES*16
    int n = idx >> 4, c = idx & 15;
    int g = __ldg(s2g + __ldg(n2s + n));
    float4 v = ((const float4*)(g_x + (size_t)n * 64))[c];
    float* o = g_gsum + g * 64 + c * 4;
    atomicAdd(o + 0, v.x);
    atomicAdd(o + 1, v.y);
    atomicAdd(o + 2, v.z);
    atomicAdd(o + 3, v.w);
}

// ---------------- MLP head ----------------------------------------------------
__global__ void k_head(const float* __restrict__ w1, const float* __restrict__ b1,
                       const float* __restrict__ w2, const float* __restrict__ b2,
                       const float* __restrict__ w3, const float* __restrict__ b3,
                       float* __restrict__ out) {
    int g = threadIdx.x;
    if (g >= 64) return;
    const float* h0 = g_gsum + g * 64;
    float h1[32];
    #pragma unroll 4
    for (int o = 0; o < 32; o++) {
        float acc = b1[o];
        #pragma unroll
        for (int k = 0; k < 64; k++) acc += h0[k] * w1[o * 64 + k];
        h1[o] = elu_(acc);
    }
    float h2[16];
    #pragma unroll
    for (int p = 0; p < 16; p++) {
        float acc = b2[p];
        #pragma unroll
        for (int o = 0; o < 32; o++) acc += h1[o] * w2[p * 32 + o];
        h2[p] = elu_(acc);
    }
    float acc = b3[0];
    #pragma unroll
    for (int q = 0; q < 16; q++) acc += h2[q] * w3[q];
    out[g] = acc;
}

// ---------------- launch -------------------------------------------------------
extern "C" void kernel_launch(void* const* d_in, const int* in_sizes, int n_in,
                              void* d_out, int out_size) {
    const int*   z    = (const int*)d_in[0];
    const int*   ei   = (const int*)d_in[1];
    const int*   n2s  = (const int*)d_in[2];
    const int*   s2g  = (const int*)d_in[3];
    const float* ztab = (const float*)d_in[4];
    const float* tfW  = (const float*)d_in[5];
    const float* tfb  = (const float*)d_in[6];
    const float* ggcW = (const float*)d_in[7];
    const float* wih  = (const float*)d_in[8];
    const float* whh  = (const float*)d_in[9];
    const float* bih  = (const float*)d_in[10];
    const float* bhh  = (const float*)d_in[11];
    const float* w1   = (const float*)d_in[12];
    const float* b1   = (const float*)d_in[13];
    const float* w2   = (const float*)d_in[14];
    const float* b2   = (const float*)d_in[15];
    const float* w3   = (const float*)d_in[16];
    const float* b3   = (const float*)d_in[17];
    const int* src = ei;
    const int* dst = ei + N_EDGES;

    cudaFuncSetAttribute(k_gru, cudaFuncAttributeMaxDynamicSharedMemorySize, 100352);

    const int NB = (N_NODES + 255) / 256;  // 1954

    k_zero_agg<<<31250, 256>>>();
    k_pre1<<<189, 256>>>(ztab, tfW, tfb, ggcW);
    k_pre2<<<100, 256>>>(ggcW);
    k_layer0<<<31250, 256>>>(z, ztab);

    for (int l = 0; l < 5; l++) {
        if (l > 0) k_pre<<<NB, 256>>>(z, tfW, l - 1);
        k_scatter<<<78125, 256>>>(src, dst);
        k_gru<<<NB, 256, 99840>>>(wih + l * 12288, whh + l * 12288,
                                  bih + l * 192, bhh + l * 192);
    }

    k_zero_gsum<<<16, 256>>>();
    k_pool<<<31250, 256>>>(n2s, s2g);
    k_head<<<1, 64>>>(w1, b1, w2, b2, w3, b3, (float*)d_out);
}